// round 16
// baseline (speedup 1.0000x reference)
#include <cuda_runtime.h>

// ActiveParticles step, N=4096 — ONE kernel (128 CTAs x 1024 threads).
// Phase A: zero cell counts.            [grid barrier]
// Phase B: pack + bin + mean partials.  [grid barrier]
// Phase C: per-warp 3x3 scan (main sums + RS-candidate gather w/ local translation),
//          epilogue, local 3-iteration collision solve (3-hop closure < RS).
// Output: [5, N, 2] f32 = {new_p, new_u, orientation_sums, leftturns, rightturns}.

#define NMAX  4096
#define GDIM  64
#define CELLS (GDIM * GDIM)
#define CAP   64       // max particles per cell (peak cell Poisson mean ~12.8)
#define CCAP  64       // max solve candidates (RS mean ~14.4 at peak density)
#define NBLK  128      // CTAs: <= 148 SMs -> barrier co-residency unconditional

// Span [-2.24e-3, 2.24e-3], cell 7e-5 >= RS (4.2e-5) >= ROC (2.815e-5).
// Clamped mapping is monotone & non-expanding -> 3x3 cells cover any radius <= cell.
#define XMIN  (-2.24e-3f)
#define INVCS (14285.714285714286f)   // 1 / 7e-5

static __device__ float2   g_part[NBLK];       // per-CTA mean partials
static __device__ float4   g_pu[NMAX];         // (p.x,p.y,u.x,u.y)
static __device__ unsigned g_cellcnt[CELLS];
static __device__ int      g_celllist[CELLS * CAP];
static __device__ volatile unsigned g_gen;     // barrier generation
static __device__ unsigned g_count;            // barrier arrivals

__device__ __forceinline__ float wsum(float v) {
#pragma unroll
    for (int o = 16; o; o >>= 1) v += __shfl_xor_sync(0xffffffffu, v, o);
    return v;
}

__device__ __forceinline__ float anglewrap(float diff) {
    const float PI_F = 3.1415927410125732f;
    if (diff <= -PI_F) diff = diff - PI_F * floorf(diff / PI_F);  // jnp.mod(diff, PI)
    if (diff >= PI_F) diff -= 2.0f * PI_F;
    return diff;
}

__device__ __forceinline__ float anglediff(float ax, float ay, float bx, float by) {
    return anglewrap(atan2f(ay, ax) - atan2f(by, bx));
}

__device__ __forceinline__ int cell_of(float x, float y) {
    int cx = __float2int_rd((x - XMIN) * INVCS);
    int cy = __float2int_rd((y - XMIN) * INVCS);
    cx = max(0, min(GDIM - 1, cx));
    cy = max(0, min(GDIM - 1, cy));
    return cy * GDIM + cx;
}

// Translation constants (exact op order kept from passing rounds)
#define DTV  ((float)(0.2 * 5e-7))
#define CSH  ((float)0.7071067811865476)        // sqrt(0.5)
#define C2T  ((float)1.6733200530681511e-07)    // sqrt(2*DT_trans)
#define SDT  ((float)0.4472135954999579)        // sqrt(dt)

// 128-CTA grid barrier (co-resident by construction). thread0's __threadfence
// is gpu-scope (CCTL.IVALL): flushes writes to L2 + invalidates this SM's L1.
__device__ __forceinline__ void grid_sync(unsigned nb) {
    __syncthreads();
    if (threadIdx.x == 0) {
        unsigned my = g_gen;                     // read BEFORE arriving
        __threadfence();
        if (atomicAdd(&g_count, 1u) == nb - 1u) {
            g_count = 0u;
            __threadfence();
            g_gen = my + 1u;
        } else {
            while (g_gen == my) __nanosleep(32);
        }
        __threadfence();
    }
    __syncthreads();
}

__global__ void __launch_bounds__(1024) step_kernel(
        const float2* __restrict__ pos, const float2* __restrict__ ori,
        const float* __restrict__ deltas, const float* __restrict__ rnoise,
        const float2* __restrict__ tn, float* __restrict__ out,
        int n, unsigned nb) {
    __shared__ float2 s_cand[32][CCAP];          // 16 KB: translated candidates

    const int tid  = threadIdx.x;
    const int bid  = blockIdx.x;
    const int lane = tid & 31;
    const int w    = tid >> 5;
    const int gtid = bid * 1024 + tid;

    // ---- Phase A: zero cell counts ----------------------------------------------
    if (gtid < CELLS) g_cellcnt[gtid] = 0u;
    grid_sync(nb);

    // ---- Phase B: pack + bin + per-block mean partial (warp 0 of each block) -----
    if (w == 0) {
        const int i = bid * 32 + lane;           // this block's 32 particles
        float px = 0.f, py = 0.f;
        if (i < n) {
            float2 pp = pos[i], uu = ori[i];
            g_pu[i] = make_float4(pp.x, pp.y, uu.x, uu.y);
            int c = cell_of(pp.x, pp.y);
            unsigned slot = atomicAdd(&g_cellcnt[c], 1u);
            g_celllist[c * CAP + min(slot, (unsigned)(CAP - 1))] = i;
            px = pp.x; py = pp.y;
        }
        px = wsum(px); py = wsum(py);
        if (lane == 0) g_part[bid] = make_float2(px, py);
    }
    grid_sync(nb);

    // ---- Phase C: main pass + local collision solve (warp per particle) ----------
    const int i = bid * 32 + w;
    if (i >= n) return;

    const float4 me = g_pu[i];
    const float pix = me.x, piy = me.y, uix = me.z, uiy = me.w;

    // translated own position (reference: p + dt*V*u + trans noise)
    float2 ti = tn[i];
    const float tpix = pix + DTV * uix + ((ti.x * CSH) * C2T) * SDT;
    const float tpiy = piy + DTV * uiy + ((ti.y * CSH) * C2T) * SDT;
    if (lane == 0) s_cand[w][0] = make_float2(tpix, tpiy);  // slot 0 = self
    int ccnt = 1;
    unsigned nearAny = 0u;

    const float RR2  = (float)(8e-6 * 8e-6);
    const float ROCf = (float)(2.5e-5 + 3.15e-6);
    const float ROC2 = ROCf * ROCf;
    const unsigned uRR2 = __float_as_uint(RR2);
    const float RS2 = 4.2e-5f * 4.2e-5f;         // solve gather radius (3-hop closure)
    const float RN2 = 2.1e-5f * 2.1e-5f;         // direct-hit closure radius

    float nr = 0.f, srx = 0.f, sry = 0.f, osx = 0.f, osy = 0.f;

    const int c0 = cell_of(pix, piy);
    const int cx = c0 & (GDIM - 1), cy = c0 >> 6;
#pragma unroll
    for (int ky = 0; ky < 3; ky++) {
#pragma unroll
        for (int kx = 0; kx < 3; kx++) {
            int rx = cx + kx - 1, ry = cy + ky - 1;
            if ((unsigned)rx >= (unsigned)GDIM || (unsigned)ry >= (unsigned)GDIM) continue;
            int cc = ry * GDIM + rx;
            int cnt = min((int)g_cellcnt[cc], CAP);
            int base = cc * CAP;
            for (int tb = 0; tb < cnt; tb += 32) {           // warp-uniform trip count
                int t = tb + lane;
                bool act = t < cnt;
                int j = act ? g_celllist[base + t] : 0;
                float4 aj = g_pu[j];
                float dx = aj.x - pix, dyv = aj.y - piy;
                float d2 = fmaf(dx, dx, dyv * dyv);
                if (act && d2 <= ROC2) {                     // mask_ro (includes self)
                    osx += aj.z; osy += aj.w;
                    if ((__float_as_uint(d2) - 1u) < uRR2) { // 0 < d2 <= RR2
                        // in_front: wrap(angle(dir)-angle(u_j)) < pi/2
                        //   <=> !(dot<=0 && cross>=0)
                        float cc2 = dx * aj.z + dyv * aj.w;
                        float ss2 = aj.z * dyv - aj.w * dx;
                        if (!(cc2 <= 0.0f && ss2 >= 0.0f)) { nr += 1.f; srx += aj.x; sry += aj.y; }
                    }
                }
                bool acc = act && (j != i) && (d2 <= RS2);
                unsigned mask = __ballot_sync(0xffffffffu, acc);
                if (acc) {
                    int slot = ccnt + __popc(mask & ((1u << lane) - 1u));
                    if (slot < CCAP) {
                        float2 tj = tn[j];
                        float tjx = aj.x + DTV * aj.z + ((tj.x * CSH) * C2T) * SDT;
                        float tjy = aj.y + DTV * aj.w + ((tj.y * CSH) * C2T) * SDT;
                        s_cand[w][slot] = make_float2(tjx, tjy);
                    }
                }
                ccnt += __popc(mask);
                nearAny |= __ballot_sync(0xffffffffu, act && (j != i) && d2 <= RN2);
            }
        }
    }
    ccnt = min(ccnt, CCAP);
    nr = wsum(nr); srx = wsum(srx); sry = wsum(sry); osx = wsum(osx); osy = wsum(osy);

    // ---- epilogue (all lanes) ----
    // cms: lane-parallel fixed-order reduction of 128 per-block partials
    float cmx = 0.f, cmy = 0.f;
#pragma unroll
    for (int k = 0; k < NBLK / 32; k++) {
        float2 v = g_part[lane + k * 32];
        cmx += v.x; cmy += v.y;
    }
    cmx = wsum(cmx); cmy = wsum(cmy);
    float invn = 1.0f / fmaxf((float)n, 1.0f);   // max(n_a,1), n_a=n (mask_ra all-true)
    float Psx = cmx * invn - pix;                // sign(n_a)==1
    float Psy = cmy * invn - piy;

    float sgn = (nr > 0.f) ? 1.0f : 0.0f;
    float invr = 1.0f / fmaxf(nr, 1.0f);
    float dax = -(srx * invr - pix * sgn);
    float day = -(sry * invr - piy * sgn);

    float Delta = __ldg(&deltas[0]);
    float cd = cosf(Delta), sd = sinf(Delta);
    float lx = Psx * cd - Psy * sd, ly = Psx * sd + Psy * cd;   // Ps*e^{+iD}
    float rx = Psx * cd + Psy * sd, ry = Psy * cd - Psx * sd;   // Ps*e^{-iD}

    const float EPSF = 1e-14f;
    float nbn = fmaxf(sqrtf(osx * osx + osy * osy + 1e-30f), EPSF);
    float naL = fmaxf(sqrtf(lx * lx + ly * ly + 1e-30f), EPSF);
    float naR = fmaxf(sqrtf(rx * rx + ry * ry + 1e-30f), EPSF);
    float csL = (lx * osx + ly * osy) / (naL * nbn);
    float csR = (rx * osx + ry * osy) / (naR * nbn);
    bool left_closer = (csL >= csR);
    float bx = left_closer ? lx : rx;
    float by = left_closer ? ly : ry;

    float d_abs = sqrtf(dax * dax + day * day);
    float ang;
    if (d_abs > 0.f) {
        ang = anglediff(dax, day, uix, uiy);
    } else {
        float babs = sqrtf(bx * bx + by * by);
        float bsx = (babs > 0.f) ? bx : 1.0f;
        float bsy = (babs > 0.f) ? by : 0.0f;
        ang = anglediff(bsx, bsy, uix, uiy);
    }

    const float C1   = (float)(0.2 * 25.0 * 0.0028);     // dt*Gamma*DR
    const float S2DR = (float)0.07483314773547883;       // sqrt(2*DR)
    float phi = C1 * sinf(ang) + rnoise[i] * S2DR * SDT;
    float cr = cosf(phi), sr = sinf(phi);
    float nux = uix * cr - uiy * sr;
    float nuy = uix * sr + uiy * cr;

    // ---- local collision solve: 3 reference iterations on the RS-candidate set ---
    float2 newp = make_float2(tpix, tpiy);
    const float TH2 = (float)(2.0 * 3.15e-6) * (float)(2.0 * 3.15e-6);
    const float C21 = (float)(2.1 * 3.15e-6);
    const unsigned uTH2 = __float_as_uint(TH2);
    __syncwarp();
    if (nearAny) {                               // no direct hit possible otherwise
#pragma unroll
        for (int it = 0; it < 3; it++) {
            float2 own[2];
#pragma unroll
            for (int o = 0; o < 2; o++) {
                int s2 = lane + o * 32;
                own[o] = (s2 < ccnt) ? s_cand[w][s2] : make_float2(1e9f, 1e9f);
            }
            float mvx[2] = {0.f, 0.f}, mvy[2] = {0.f, 0.f};
            for (int t = 0; t < ccnt; t++) {
                float2 d = s_cand[w][t];                 // broadcast read
#pragma unroll
                for (int o = 0; o < 2; o++) {
                    float dx = d.x - own[o].x, dyv = d.y - own[o].y;
                    float d2 = fmaf(dx, dx, dyv * dyv);
                    if ((__float_as_uint(d2) - 1u) < uTH2) {  // 0 < d2 <= 2RC
                        float ab = sqrtf(d2);
                        float sc = (C21 - ab) * 0.5f / ab;
                        mvx[o] += dx * sc; mvy[o] += dyv * sc;
                    }
                }
            }
            __syncwarp();
#pragma unroll
            for (int o = 0; o < 2; o++) {
                int s2 = lane + o * 32;
                if (s2 < ccnt)
                    s_cand[w][s2] = make_float2(own[o].x - mvx[o], own[o].y - mvy[o]);
            }
            __syncwarp();
        }
        newp = s_cand[w][0];
    }

    if (lane == 0) {
        int b = 2 * n;
        out[0 * b + 2 * i + 0] = newp.x;  out[0 * b + 2 * i + 1] = newp.y;
        out[1 * b + 2 * i + 0] = nux;     out[1 * b + 2 * i + 1] = nuy;
        out[2 * b + 2 * i + 0] = osx;     out[2 * b + 2 * i + 1] = osy;
        out[3 * b + 2 * i + 0] = lx;      out[3 * b + 2 * i + 1] = ly;
        out[4 * b + 2 * i + 0] = rx;      out[4 * b + 2 * i + 1] = ry;
    }
}

extern "C" void kernel_launch(void* const* d_in, const int* in_sizes, int n_in,
                              void* d_out, int out_size) {
    const float* pos = (const float*)d_in[0];
    const float* ori = (const float*)d_in[1];
    const float* del = (const float*)d_in[2];
    const float* rno = (const float*)d_in[3];
    const float* tno = (const float*)d_in[4];
    float* out = (float*)d_out;
    const int n = in_sizes[3];                   // rot_noise has N elements

    const unsigned nb = (unsigned)((n + 31) / 32);   // 128 CTAs, warp per particle
    step_kernel<<<nb, 1024>>>((const float2*)pos, (const float2*)ori, del, rno,
                              (const float2*)tno, out, n, nb);
}

// round 17
// speedup vs baseline: 1.0329x; 1.0329x over previous
#include <cuda_runtime.h>

// ActiveParticles step, N=4096 — TWO kernels (R15 structure + payload-in-cell-list).
// K1 bin:   zero counts -> 4-CTA grid barrier -> bin payloads + mean partials.
//           Cell list stores (p,u) AND the translated position directly, so the
//           main kernel has NO index indirection (chain depth 1 per trip).
// K2 fused: per-warp 3x3 scan (main sums + RS-candidate gather), epilogue,
//           local 3-iteration collision solve (3-hop closure < RS gather).
// Output: [5, N, 2] f32 = {new_p, new_u, orientation_sums, leftturns, rightturns}.

#define NMAX  4096
#define GDIM  64
#define CELLS (GDIM * GDIM)
#define CAP   64       // max particles per cell (peak cell Poisson mean ~12.8)
#define CCAP  64       // max solve candidates (RS mean ~14.4 at peak density)

// Span [-2.24e-3, 2.24e-3], cell 7e-5 >= RS (4.2e-5) >= ROC (2.815e-5).
// Clamped mapping is monotone & non-expanding -> 3x3 cells cover any radius <= cell.
#define XMIN  (-2.24e-3f)
#define INVCS (14285.714285714286f)   // 1 / 7e-5

static __device__ float2   g_part[8];              // per-CTA mean partials from bin
static __device__ unsigned g_cellcnt[CELLS];
static __device__ float4   g_cellpu[CELLS * CAP];  // payload: (p.x,p.y,u.x,u.y)
static __device__ float2   g_celltp[CELLS * CAP];  // payload: translated position
static __device__ volatile unsigned g_gen;         // tiny grid barrier (bin only)
static __device__ unsigned g_count;

__device__ __forceinline__ float wsum(float v) {
#pragma unroll
    for (int o = 16; o; o >>= 1) v += __shfl_xor_sync(0xffffffffu, v, o);
    return v;
}

__device__ __forceinline__ float anglewrap(float diff) {
    const float PI_F = 3.1415927410125732f;
    if (diff <= -PI_F) diff = diff - PI_F * floorf(diff / PI_F);  // jnp.mod(diff, PI)
    if (diff >= PI_F) diff -= 2.0f * PI_F;
    return diff;
}

__device__ __forceinline__ float anglediff(float ax, float ay, float bx, float by) {
    return anglewrap(atan2f(ay, ax) - atan2f(by, bx));
}

__device__ __forceinline__ int cell_of(float x, float y) {
    int cx = __float2int_rd((x - XMIN) * INVCS);
    int cy = __float2int_rd((y - XMIN) * INVCS);
    cx = max(0, min(GDIM - 1, cx));
    cy = max(0, min(GDIM - 1, cy));
    return cy * GDIM + cx;
}

// Translation constants (exact op order kept from passing rounds)
#define DTV  ((float)(0.2 * 5e-7))
#define CSH  ((float)0.7071067811865476)        // sqrt(0.5)
#define C2T  ((float)1.6733200530681511e-07)    // sqrt(2*DT_trans)
#define SDT  ((float)0.4472135954999579)        // sqrt(dt)

__device__ __forceinline__ void grid_sync(unsigned nb) {
    __syncthreads();
    if (threadIdx.x == 0) {
        unsigned my = g_gen;
        __threadfence();
        if (atomicAdd(&g_count, 1u) == nb - 1u) {
            g_count = 0u;
            __threadfence();
            g_gen = my + 1u;
        } else {
            while (g_gen == my) __nanosleep(32);
        }
        __threadfence();
    }
    __syncthreads();
}

// ---- K1: zero counts -> barrier -> bin payloads + per-CTA mean partials ----------
__global__ void __launch_bounds__(1024) bin_kernel(const float2* __restrict__ p,
                                                   const float2* __restrict__ u,
                                                   const float2* __restrict__ tn,
                                                   int n, unsigned nb) {
    __shared__ float2 sr[32];
    const int gtid = blockIdx.x * 1024 + threadIdx.x;
    const int lane = threadIdx.x & 31, w = threadIdx.x >> 5;

    if (gtid < CELLS) g_cellcnt[gtid] = 0u;
    grid_sync(nb);                               // tiny: nb CTAs (=4), sub-us

    float px = 0.f, py = 0.f;
    if (gtid < n) {
        float2 pp = p[gtid], uu = u[gtid];
        float2 tt = tn[gtid];
        int c = cell_of(pp.x, pp.y);
        unsigned slot = atomicAdd(&g_cellcnt[c], 1u);
        int idx = c * CAP + (int)min(slot, (unsigned)(CAP - 1));
        g_cellpu[idx] = make_float4(pp.x, pp.y, uu.x, uu.y);
        // translated position (reference: p + dt*V*u + trans noise)
        float tx = pp.x + DTV * uu.x + ((tt.x * CSH) * C2T) * SDT;
        float ty = pp.y + DTV * uu.y + ((tt.y * CSH) * C2T) * SDT;
        g_celltp[idx] = make_float2(tx, ty);
        px = pp.x; py = pp.y;
    }
    px = wsum(px); py = wsum(py);
    if (lane == 0) sr[w] = make_float2(px, py);
    __syncthreads();
    if (threadIdx.x == 0) {
        float ax = 0.f, ay = 0.f;
#pragma unroll
        for (int k = 0; k < 32; k++) { ax += sr[k].x; ay += sr[k].y; }
        g_part[blockIdx.x] = make_float2(ax, ay);
    }
}

// ---- K2: fused main + local 3-iteration collision solve --------------------------
__global__ void __launch_bounds__(1024) fused_kernel(
        const float2* __restrict__ pos, const float2* __restrict__ ori,
        const float* __restrict__ deltas, const float* __restrict__ rnoise,
        const float2* __restrict__ tn, float* __restrict__ out, int n, int nbin) {
    __shared__ float2 s_cand[32][CCAP];          // 16 KB: translated candidates

    const int lane = threadIdx.x & 31;
    const int w    = threadIdx.x >> 5;
    const int i    = blockIdx.x * 32 + w;        // warp per particle
    if (i >= n) return;

    const float2 mp = pos[i];
    const float2 mu = ori[i];
    const float pix = mp.x, piy = mp.y, uix = mu.x, uiy = mu.y;

    // translated own position (same formula/op-order as bin)
    float2 ti = tn[i];
    const float tpix = pix + DTV * uix + ((ti.x * CSH) * C2T) * SDT;
    const float tpiy = piy + DTV * uiy + ((ti.y * CSH) * C2T) * SDT;
    if (lane == 0) s_cand[w][0] = make_float2(tpix, tpiy);  // slot 0 = self
    int ccnt = 1;
    bool nearFlag = false;

    const float RR2  = (float)(8e-6 * 8e-6);
    const float ROCf = (float)(2.5e-5 + 3.15e-6);
    const float ROC2 = ROCf * ROCf;
    const unsigned uRR2 = __float_as_uint(RR2);
    const float RS2 = 4.2e-5f * 4.2e-5f;         // solve gather radius (3-hop closure)
    const unsigned uRS2 = __float_as_uint(RS2);
    const float RN2 = 2.1e-5f * 2.1e-5f;         // direct-hit closure radius

    float nr = 0.f, srx = 0.f, sry = 0.f, osx = 0.f, osy = 0.f;

    const int c0 = cell_of(pix, piy);
    const int cx = c0 & (GDIM - 1), cy = c0 >> 6;
#pragma unroll
    for (int ky = 0; ky < 3; ky++) {
#pragma unroll
        for (int kx = 0; kx < 3; kx++) {
            int rx = cx + kx - 1, ry = cy + ky - 1;
            if ((unsigned)rx >= (unsigned)GDIM || (unsigned)ry >= (unsigned)GDIM) continue;
            int cc = ry * GDIM + rx;
            int cnt = min((int)g_cellcnt[cc], CAP);
            int base = cc * CAP;
            for (int tb = 0; tb < cnt; tb += 32) {           // warp-uniform trip count
                int t = tb + lane;
                bool act = t < cnt;
                // Two INDEPENDENT predicated loads (no index indirection).
                float4 aj = act ? g_cellpu[base + t] : make_float4(1e9f, 1e9f, 0.f, 0.f);
                float2 tj = act ? g_celltp[base + t] : make_float2(1e9f, 1e9f);
                float dx = aj.x - pix, dyv = aj.y - piy;
                float d2 = fmaf(dx, dx, dyv * dyv);
                if (d2 <= ROC2) {                            // mask_ro (includes self)
                    osx += aj.z; osy += aj.w;
                    if ((__float_as_uint(d2) - 1u) < uRR2) { // 0 < d2 <= RR2 (excl self)
                        // in_front: wrap(angle(dir)-angle(u_j)) < pi/2
                        //   <=> !(dot<=0 && cross>=0)
                        float cc2 = dx * aj.z + dyv * aj.w;
                        float ss2 = aj.z * dyv - aj.w * dx;
                        if (!(cc2 <= 0.0f && ss2 >= 0.0f)) { nr += 1.f; srx += aj.x; sry += aj.y; }
                    }
                }
                // gather: 0 < d2 <= RS2 (self excluded by d2==0 -> wraps to UINT_MAX)
                bool acc = (__float_as_uint(d2) - 1u) < uRS2;
                unsigned mask = __ballot_sync(0xffffffffu, acc);
                if (acc) {
                    int slot = ccnt + __popc(mask & ((1u << lane) - 1u));
                    if (slot < CCAP) s_cand[w][slot] = tj;   // payload already translated
                }
                ccnt += __popc(mask);
                nearFlag |= (d2 > 0.f) && (d2 <= RN2);
            }
        }
    }
    ccnt = min(ccnt, CCAP);
    unsigned nearAny = __ballot_sync(0xffffffffu, nearFlag);
    nr = wsum(nr); srx = wsum(srx); sry = wsum(sry); osx = wsum(osx); osy = wsum(osy);

    // ---- epilogue (all lanes redundant) ----
    float cmx = 0.f, cmy = 0.f;
    for (int k = 0; k < nbin; k++) { float2 v = g_part[k]; cmx += v.x; cmy += v.y; }
    float invn = 1.0f / fmaxf((float)n, 1.0f);   // max(n_a,1), n_a=n (mask_ra all-true)
    float Psx = cmx * invn - pix;                // sign(n_a)==1
    float Psy = cmy * invn - piy;

    float sgn = (nr > 0.f) ? 1.0f : 0.0f;
    float invr = 1.0f / fmaxf(nr, 1.0f);
    float dax = -(srx * invr - pix * sgn);
    float day = -(sry * invr - piy * sgn);

    float Delta = __ldg(&deltas[0]);
    float cd = cosf(Delta), sd = sinf(Delta);
    float lx = Psx * cd - Psy * sd, ly = Psx * sd + Psy * cd;   // Ps*e^{+iD}
    float rx = Psx * cd + Psy * sd, ry = Psy * cd - Psx * sd;   // Ps*e^{-iD}

    const float EPSF = 1e-14f;
    float nbn = fmaxf(sqrtf(osx * osx + osy * osy + 1e-30f), EPSF);
    float naL = fmaxf(sqrtf(lx * lx + ly * ly + 1e-30f), EPSF);
    float naR = fmaxf(sqrtf(rx * rx + ry * ry + 1e-30f), EPSF);
    float csL = (lx * osx + ly * osy) / (naL * nbn);
    float csR = (rx * osx + ry * osy) / (naR * nbn);
    bool left_closer = (csL >= csR);
    float bx = left_closer ? lx : rx;
    float by = left_closer ? ly : ry;

    float d_abs = sqrtf(dax * dax + day * day);
    float ang;
    if (d_abs > 0.f) {
        ang = anglediff(dax, day, uix, uiy);
    } else {
        float babs = sqrtf(bx * bx + by * by);
        float bsx = (babs > 0.f) ? bx : 1.0f;
        float bsy = (babs > 0.f) ? by : 0.0f;
        ang = anglediff(bsx, bsy, uix, uiy);
    }

    const float C1   = (float)(0.2 * 25.0 * 0.0028);     // dt*Gamma*DR
    const float S2DR = (float)0.07483314773547883;       // sqrt(2*DR)
    float phi = C1 * sinf(ang) + rnoise[i] * S2DR * SDT;
    float cr = cosf(phi), sr = sinf(phi);
    float nux = uix * cr - uiy * sr;
    float nuy = uix * sr + uiy * cr;

    // ---- local collision solve: 3 reference iterations on the RS-candidate set ---
    float2 newp = make_float2(tpix, tpiy);
    const float TH2 = (float)(2.0 * 3.15e-6) * (float)(2.0 * 3.15e-6);
    const float C21 = (float)(2.1 * 3.15e-6);
    const unsigned uTH2 = __float_as_uint(TH2);
    __syncwarp();
    if (nearAny) {                               // no direct hit possible otherwise
#pragma unroll
        for (int it = 0; it < 3; it++) {
            float2 own[2];
#pragma unroll
            for (int o = 0; o < 2; o++) {
                int s2 = lane + o * 32;
                own[o] = (s2 < ccnt) ? s_cand[w][s2] : make_float2(1e9f, 1e9f);
            }
            float mvx[2] = {0.f, 0.f}, mvy[2] = {0.f, 0.f};
            for (int t = 0; t < ccnt; t++) {
                float2 d = s_cand[w][t];                 // broadcast read
#pragma unroll
                for (int o = 0; o < 2; o++) {
                    float dx = d.x - own[o].x, dyv = d.y - own[o].y;
                    float d2 = fmaf(dx, dx, dyv * dyv);
                    if ((__float_as_uint(d2) - 1u) < uTH2) {  // 0 < d2 <= 2RC
                        float ab = sqrtf(d2);
                        float sc = (C21 - ab) * 0.5f / ab;
                        mvx[o] += dx * sc; mvy[o] += dyv * sc;
                    }
                }
            }
            __syncwarp();
#pragma unroll
            for (int o = 0; o < 2; o++) {
                int s2 = lane + o * 32;
                if (s2 < ccnt)
                    s_cand[w][s2] = make_float2(own[o].x - mvx[o], own[o].y - mvy[o]);
            }
            __syncwarp();
        }
        newp = s_cand[w][0];
    }

    if (lane == 0) {
        int b = 2 * n;
        out[0 * b + 2 * i + 0] = newp.x;  out[0 * b + 2 * i + 1] = newp.y;
        out[1 * b + 2 * i + 0] = nux;     out[1 * b + 2 * i + 1] = nuy;
        out[2 * b + 2 * i + 0] = osx;     out[2 * b + 2 * i + 1] = osy;
        out[3 * b + 2 * i + 0] = lx;      out[3 * b + 2 * i + 1] = ly;
        out[4 * b + 2 * i + 0] = rx;      out[4 * b + 2 * i + 1] = ry;
    }
}

extern "C" void kernel_launch(void* const* d_in, const int* in_sizes, int n_in,
                              void* d_out, int out_size) {
    const float* pos = (const float*)d_in[0];
    const float* ori = (const float*)d_in[1];
    const float* del = (const float*)d_in[2];
    const float* rno = (const float*)d_in[3];
    const float* tno = (const float*)d_in[4];
    float* out = (float*)d_out;
    const int n = in_sizes[3];                   // rot_noise has N elements

    int nbin = (n + 1023) / 1024;                // CTAs for bin (covers CELLS too: 4)
    if (nbin < (CELLS + 1023) / 1024) nbin = (CELLS + 1023) / 1024;
    const int nfuse = (n + 31) / 32;             // 128 CTAs x 1024 thr (warp/particle)

    bin_kernel<<<nbin, 1024>>>((const float2*)pos, (const float2*)ori,
                               (const float2*)tno, n, (unsigned)nbin);
    fused_kernel<<<nfuse, 1024>>>((const float2*)pos, (const float2*)ori,
                                  del, rno, (const float2*)tno, out, n, nbin);
}